// round 1
// baseline (speedup 1.0000x reference)
#include <cuda_runtime.h>
#include <math.h>

#define FULLMASK 0xffffffffu

#define Bc 8
#define Tc 24
#define Nc 1000
#define Ec 1000
#define F_INc 16
#define C_RAWc 8
#define DMc 32
#define HCc 32
#define TKc 32
#define PREDc 12
#define LAMc 0.3f
#define EPSc 1e-8f
#define MAXD 64
#define MAXEN 21

// ---------------- scratch (device globals; no allocation) ----------------
__device__ int   g_edge_nodes[Ec * MAXEN];
__device__ int   g_edge_cnt[Ec];
__device__ int   g_node_edges[Nc * MAXD];
__device__ int   g_node_deg[Nc];
__device__ float g_feat[Bc * Nc * 16];
__device__ float g_msum[Bc * Ec];
__device__ float g_Wd[Bc * Ec];
__device__ float g_dvi[Bc * Nc];
__device__ float g_xp[Bc * Tc * Nc * DMc];   // projected node features
__device__ float g_u[Bc * Tc * Ec * DMc];    // edge features (scaled)
__device__ float g_seq[Bc * Nc * Tc * HCc];  // LSTM input sequences

// ---------------- math helpers ----------------
__device__ __forceinline__ float sigmf(float x) { return __fdividef(1.f, 1.f + __expf(-x)); }
__device__ __forceinline__ float tanhf_(float x) { return 2.f * sigmf(2.f * x) - 1.f; }
__device__ __forceinline__ float siluf(float x) { return x * sigmf(x); }

// ---------------- adjacency build ----------------
__global__ void k_zero_deg() {
    int i = blockIdx.x * blockDim.x + threadIdx.x;
    if (i < Nc) g_node_deg[i] = 0;
}

__global__ void k_build_edges(const int* __restrict__ members,
                              const int* __restrict__ centers,
                              const int* __restrict__ offsets) {
    int e = blockIdx.x * blockDim.x + threadIdx.x;
    if (e >= Ec) return;
    int s = offsets[e], t = offsets[e + 1];
    int list[MAXEN];
    int cnt = 0;
    for (int m = s; m < t && cnt < MAXEN; m++) {
        int n = members[m];
        bool dup = false;
        for (int k = 0; k < cnt; k++) if (list[k] == n) { dup = true; break; }
        if (!dup) list[cnt++] = n;
    }
    {
        int c = centers[e];
        bool dup = false;
        for (int k = 0; k < cnt; k++) if (list[k] == c) { dup = true; break; }
        if (!dup && cnt < MAXEN) list[cnt++] = c;
    }
    g_edge_cnt[e] = cnt;
    for (int k = 0; k < cnt; k++) {
        int n = list[k];
        g_edge_nodes[e * MAXEN + k] = n;
        int pos = atomicAdd(&g_node_deg[n], 1);
        if (pos < MAXD) g_node_edges[n * MAXD + pos] = e;
    }
}

__global__ void k_sort_nodes() {
    int n = blockIdx.x * blockDim.x + threadIdx.x;
    if (n >= Nc) return;
    int d = g_node_deg[n];
    if (d > MAXD) d = MAXD;
    g_node_deg[n] = d;
    int* L = g_node_edges + n * MAXD;
    for (int i = 1; i < d; i++) {
        int key = L[i];
        int j = i - 1;
        while (j >= 0 && L[j] > key) { L[j + 1] = L[j]; j--; }
        L[j + 1] = key;
    }
}

// ---------------- dynamic features: mean/std over T ----------------
__global__ void k_feat(const float* __restrict__ xraw) {
    int idx = blockIdx.x * blockDim.x + threadIdx.x;  // Bc*Nc*C_RAWc = 64000
    if (idx >= Bc * Nc * C_RAWc) return;
    int c = idx % C_RAWc;
    int n = (idx / C_RAWc) % Nc;
    int b = idx / (C_RAWc * Nc);
    float s1 = 0.f, s2 = 0.f;
    #pragma unroll
    for (int t = 0; t < Tc; t++) {
        float v = xraw[((b * Tc + t) * Nc + n) * C_RAWc + c];
        s1 += v; s2 += v * v;
    }
    float mean = s1 * (1.f / Tc);
    float var = s2 * (1.f / Tc) - mean * mean;
    if (var < 0.f) var = 0.f;
    g_feat[(b * Nc + n) * 16 + c] = mean;
    g_feat[(b * Nc + n) * 16 + C_RAWc + c] = sqrtf(var);
}

// ---------------- per-edge mean similarity ----------------
__global__ void k_sim(const int* __restrict__ members,
                      const int* __restrict__ centers,
                      const int* __restrict__ offsets) {
    int idx = blockIdx.x * blockDim.x + threadIdx.x;  // Bc*Ec
    if (idx >= Bc * Ec) return;
    int e = idx % Ec;
    int b = idx / Ec;
    int s = offsets[e], t = offsets[e + 1];
    int cn = centers[e];
    const float4* cf4 = (const float4*)(g_feat + (b * Nc + cn) * 16);
    float4 c0 = cf4[0], c1 = cf4[1], c2 = cf4[2], c3 = cf4[3];
    float cn2 = c0.x*c0.x + c0.y*c0.y + c0.z*c0.z + c0.w*c0.w
              + c1.x*c1.x + c1.y*c1.y + c1.z*c1.z + c1.w*c1.w
              + c2.x*c2.x + c2.y*c2.y + c2.z*c2.z + c2.w*c2.w
              + c3.x*c3.x + c3.y*c3.y + c3.z*c3.z + c3.w*c3.w;
    float cnorm = sqrtf(cn2);
    float acc = 0.f;
    for (int m = s; m < t; m++) {
        int n = members[m];
        const float4* mf4 = (const float4*)(g_feat + (b * Nc + n) * 16);
        float4 m0 = mf4[0], m1 = mf4[1], m2 = mf4[2], m3 = mf4[3];
        float dot = m0.x*c0.x + m0.y*c0.y + m0.z*c0.z + m0.w*c0.w
                  + m1.x*c1.x + m1.y*c1.y + m1.z*c1.z + m1.w*c1.w
                  + m2.x*c2.x + m2.y*c2.y + m2.z*c2.z + m2.w*c2.w
                  + m3.x*c3.x + m3.y*c3.y + m3.z*c3.z + m3.w*c3.w;
        float mn2 = m0.x*m0.x + m0.y*m0.y + m0.z*m0.z + m0.w*m0.w
                  + m1.x*m1.x + m1.y*m1.y + m1.z*m1.z + m1.w*m1.w
                  + m2.x*m2.x + m2.y*m2.y + m2.z*m2.z + m2.w*m2.w
                  + m3.x*m3.x + m3.y*m3.y + m3.z*m3.z + m3.w*m3.w;
        float sim = dot / (sqrtf(mn2) * cnorm + EPSc);
        sim = fminf(fmaxf(sim, 0.f), 1.f);
        acc += sim;
    }
    float count = (float)(t - s);
    if (count < 1.f) count = 1.f;
    g_msum[b * Ec + e] = acc / count;
}

// ---------------- per-batch min-max normalize -> Wd ----------------
__global__ void k_wd(const float* __restrict__ W) {
    int b = blockIdx.x;
    int tid = threadIdx.x;
    __shared__ float rmn[256], rmx[256];
    float mn = 1e30f, mx = -1e30f;
    for (int e = tid; e < Ec; e += 256) {
        float v = g_msum[b * Ec + e];
        mn = fminf(mn, v); mx = fmaxf(mx, v);
    }
    rmn[tid] = mn; rmx[tid] = mx;
    __syncthreads();
    for (int s = 128; s > 0; s >>= 1) {
        if (tid < s) {
            rmn[tid] = fminf(rmn[tid], rmn[tid + s]);
            rmx[tid] = fmaxf(rmx[tid], rmx[tid + s]);
        }
        __syncthreads();
    }
    mn = rmn[0]; mx = rmx[0];
    float inv = __fdividef(1.f, mx - mn + EPSc);
    for (int e = tid; e < Ec; e += 256) {
        float v = (g_msum[b * Ec + e] - mn) * inv;
        g_Wd[b * Ec + e] = W[e] * (1.f + LAMc * v);
    }
}

// ---------------- node degree weights -> dvi ----------------
__global__ void k_dvi() {
    int idx = blockIdx.x * blockDim.x + threadIdx.x;  // Bc*Nc
    if (idx >= Bc * Nc) return;
    int n = idx % Nc;
    int b = idx / Nc;
    int d = g_node_deg[n];
    float dv = 0.f;
    for (int i = 0; i < d; i++) dv += g_Wd[b * Ec + g_node_edges[n * MAXD + i]];
    dv = fmaxf(dv, EPSc);
    g_dvi[idx] = rsqrtf(dv);
}

// ---------------- input projection ----------------
__global__ void k_xp(const float* __restrict__ x,
                     const float* __restrict__ w,
                     const float* __restrict__ bias) {
    int idx = blockIdx.x * blockDim.x + threadIdx.x;  // Bc*Tc*Nc*DMc
    if (idx >= Bc * Tc * Nc * DMc) return;
    int j = idx & 31;
    int row = idx >> 5;
    float acc = bias[j];
    #pragma unroll
    for (int k = 0; k < F_INc; k++) acc += x[row * F_INc + k] * w[k * DMc + j];
    g_xp[idx] = acc;
}

// ---------------- edge gather: u = (Wd/De) * H^T (dvi*xp) ----------------
// block per ((b,t) slice, half of edges); xp slice staged in smem with dvi folded in
__global__ void k_edge_gather() {
    extern __shared__ float xs[];  // Nc*32 floats = 128000 B
    int bt = blockIdx.x >> 1;
    int part = blockIdx.x & 1;
    int b = bt / Tc;
    const float4* xp4 = (const float4*)(g_xp + (size_t)bt * Nc * DMc);
    float4* xs4 = (float4*)xs;
    for (int i = threadIdx.x; i < Nc * 8; i += blockDim.x) {
        int n = i >> 3;
        float d = g_dvi[b * Nc + n];
        float4 v = xp4[i];
        v.x *= d; v.y *= d; v.z *= d; v.w *= d;
        xs4[i] = v;
    }
    __syncthreads();
    int lane = threadIdx.x & 31;
    int w = threadIdx.x >> 5;
    int e0 = part * (Ec / 2), e1 = e0 + (Ec / 2);
    for (int e = e0 + w; e < e1; e += 8) {
        int cnt = g_edge_cnt[e];
        float acc = 0.f;
        for (int k = 0; k < cnt; k++) {
            int n = g_edge_nodes[e * MAXEN + k];
            acc += xs[n * DMc + lane];
        }
        float sc = __fdividef(g_Wd[b * Ec + e], (float)cnt);
        g_u[((size_t)bt * Ec + e) * DMc + lane] = acc * sc;
    }
}

// ---------------- node gather + conv + silu + transpose to seq ----------------
__global__ void k_node_conv(const float* __restrict__ conv_w,
                            const float* __restrict__ conv_b) {
    extern __shared__ float sm[];  // us[Ec*32] + cw[32*32] + cb[32]
    float* us = sm;
    float* cw = sm + Ec * DMc;
    float* cb = cw + DMc * HCc;
    int bt = blockIdx.x >> 1;
    int part = blockIdx.x & 1;
    int b = bt / Tc;
    int t = bt % Tc;
    const float4* u4 = (const float4*)(g_u + (size_t)bt * Ec * DMc);
    float4* us4 = (float4*)us;
    for (int i = threadIdx.x; i < Ec * 8; i += blockDim.x) us4[i] = u4[i];
    for (int i = threadIdx.x; i < DMc * HCc; i += blockDim.x) cw[i] = conv_w[i];
    if (threadIdx.x < HCc) cb[threadIdx.x] = conv_b[threadIdx.x];
    __syncthreads();
    int lane = threadIdx.x & 31;
    int w = threadIdx.x >> 5;
    int n0 = part * (Nc / 2), n1 = n0 + (Nc / 2);
    for (int n = n0 + w; n < n1; n += 8) {
        int deg = g_node_deg[n];
        float acc = 0.f;
        for (int i = 0; i < deg; i++) {
            int e = g_node_edges[n * MAXD + i];
            acc += us[e * DMc + lane];
        }
        acc *= g_dvi[b * Nc + n];
        // fused conv (32x32) via shuffles + silu
        float z = cb[lane];
        #pragma unroll
        for (int f = 0; f < DMc; f++) {
            float af = __shfl_sync(FULLMASK, acc, f);
            z += af * cw[f * HCc + lane];
        }
        g_seq[(((size_t)(b * Nc + n)) * Tc + t) * HCc + lane] = siluf(z);
    }
}

// ---------------- LSTM (fused x/h gemms) + head ----------------
// warp handles 8 rows; lane = hidden index; gates packed as float4 (i,f,g,o)
__global__ __launch_bounds__(256) void k_lstm(
    const float* __restrict__ wx, const float* __restrict__ wh,
    const float* __restrict__ lb,
    const float* __restrict__ hw1, const float* __restrict__ hb1,
    const float* __restrict__ hw2, const float* __restrict__ hb2,
    float* __restrict__ out, int Pout) {
    __shared__ float4 wxs[32 * 32];
    __shared__ float4 whs[32 * 32];
    __shared__ float4 bs[32];
    __shared__ float hw1s[32 * 32];
    __shared__ float hb1s[32];
    __shared__ float hw2s[32 * PREDc];
    __shared__ float hb2s[PREDc];

    for (int idx = threadIdx.x; idx < 1024; idx += 256) {
        int i = idx >> 5, l = idx & 31;
        wxs[idx] = make_float4(wx[i * 128 + l], wx[i * 128 + 32 + l],
                               wx[i * 128 + 64 + l], wx[i * 128 + 96 + l]);
        whs[idx] = make_float4(wh[i * 128 + l], wh[i * 128 + 32 + l],
                               wh[i * 128 + 64 + l], wh[i * 128 + 96 + l]);
        hw1s[idx] = hw1[idx];
    }
    if (threadIdx.x < 32) {
        int l = threadIdx.x;
        bs[l] = make_float4(lb[l], lb[32 + l], lb[64 + l], lb[96 + l]);
        hb1s[l] = hb1[l];
    }
    for (int idx = threadIdx.x; idx < 32 * PREDc; idx += 256) hw2s[idx] = hw2[idx];
    if (threadIdx.x < PREDc) hb2s[threadIdx.x] = hb2[threadIdx.x];
    __syncthreads();

    int lane = threadIdx.x & 31;
    int w = threadIdx.x >> 5;
    int rowbase = (blockIdx.x * 8 + w) * 8;

    float h[8], c[8];
    #pragma unroll
    for (int r = 0; r < 8; r++) { h[r] = 0.f; c[r] = 0.f; }

    for (int t = 0; t < Tc; t++) {
        float xv[8];
        #pragma unroll
        for (int r = 0; r < 8; r++)
            xv[r] = g_seq[((size_t)(rowbase + r) * Tc + t) * HCc + lane];
        float4 z[8];
        float4 bv = bs[lane];
        #pragma unroll
        for (int r = 0; r < 8; r++) z[r] = bv;
        #pragma unroll 4
        for (int i = 0; i < 32; i++) {
            float4 wxv = wxs[i * 32 + lane];
            float4 whv = whs[i * 32 + lane];
            #pragma unroll
            for (int r = 0; r < 8; r++) {
                float xi = __shfl_sync(FULLMASK, xv[r], i);
                float hi = __shfl_sync(FULLMASK, h[r], i);
                z[r].x += xi * wxv.x + hi * whv.x;
                z[r].y += xi * wxv.y + hi * whv.y;
                z[r].z += xi * wxv.z + hi * whv.z;
                z[r].w += xi * wxv.w + hi * whv.w;
            }
        }
        #pragma unroll
        for (int r = 0; r < 8; r++) {
            float ig = sigmf(z[r].x);
            float fg = sigmf(z[r].y);
            float gg = tanhf_(z[r].z);
            float og = sigmf(z[r].w);
            c[r] = fg * c[r] + ig * gg;
            h[r] = og * tanhf_(c[r]);
        }
    }

    // head: y = silu(h @ hw1 + hb1) @ hw2 + hb2
    #pragma unroll
    for (int r = 0; r < 8; r++) {
        int row = rowbase + r;
        int b = row / Nc;
        int n = row % Nc;
        float a = hb1s[lane];
        #pragma unroll 8
        for (int i = 0; i < 32; i++) {
            float hi = __shfl_sync(FULLMASK, h[r], i);
            a += hi * hw1s[i * 32 + lane];
        }
        float y1 = siluf(a);
        float o = (lane < PREDc) ? hb2s[lane] : 0.f;
        #pragma unroll 8
        for (int j = 0; j < 32; j++) {
            float yj = __shfl_sync(FULLMASK, y1, j);
            if (lane < PREDc) o += yj * hw2s[j * PREDc + lane];
        }
        if (lane < Pout) out[((size_t)b * Pout + lane) * Nc + n] = o;
    }
}

// ---------------- launch ----------------
extern "C" void kernel_launch(void* const* d_in, const int* in_sizes, int n_in,
                              void* d_out, int out_size) {
    const float* x       = (const float*)d_in[0];
    const float* xraw    = (const float*)d_in[1];
    // d_in[2] = H (dense) unused: adjacency rebuilt from members/centers/offsets
    const float* W       = (const float*)d_in[3];
    const int*   members = (const int*)d_in[4];
    const int*   centers = (const int*)d_in[5];
    const int*   offsets = (const int*)d_in[6];
    const float* ipw     = (const float*)d_in[7];
    const float* ipb     = (const float*)d_in[8];
    const float* cw      = (const float*)d_in[9];
    const float* cb      = (const float*)d_in[10];
    const float* wx      = (const float*)d_in[11];
    const float* wh      = (const float*)d_in[12];
    const float* lb      = (const float*)d_in[13];
    const float* hw1     = (const float*)d_in[14];
    const float* hb1     = (const float*)d_in[15];
    const float* hw2     = (const float*)d_in[16];
    const float* hb2     = (const float*)d_in[17];
    float* out = (float*)d_out;
    int Pout = out_size / (Bc * Nc);

    int smem_edge = Nc * DMc * sizeof(float);                       // 128000
    int smem_node = (Ec * DMc + DMc * HCc + HCc) * sizeof(float);   // 132224
    cudaFuncSetAttribute(k_edge_gather, cudaFuncAttributeMaxDynamicSharedMemorySize, smem_edge);
    cudaFuncSetAttribute(k_node_conv, cudaFuncAttributeMaxDynamicSharedMemorySize, smem_node);

    k_zero_deg<<<4, 256>>>();
    k_build_edges<<<4, 256>>>(members, centers, offsets);
    k_sort_nodes<<<4, 256>>>();
    k_feat<<<(Bc * Nc * C_RAWc + 255) / 256, 256>>>(xraw);
    k_sim<<<(Bc * Ec + 255) / 256, 256>>>(members, centers, offsets);
    k_wd<<<Bc, 256>>>(W);
    k_dvi<<<(Bc * Nc + 255) / 256, 256>>>();
    k_xp<<<(Bc * Tc * Nc * DMc + 255) / 256, 256>>>(x, ipw, ipb);
    k_edge_gather<<<Bc * Tc * 2, 256, smem_edge>>>();
    k_node_conv<<<Bc * Tc * 2, 256, smem_node>>>(cw, cb);
    k_lstm<<<Bc * Nc / 64, 256>>>(wx, wh, lb, hw1, hb1, hw2, hb2, out, Pout);
}

// round 2
// speedup vs baseline: 1.1692x; 1.1692x over previous
#include <cuda_runtime.h>
#include <math.h>

#define FULLMASK 0xffffffffu

#define Bc 8
#define Tc 24
#define Nc 1000
#define Ec 1000
#define F_INc 16
#define C_RAWc 8
#define DMc 32
#define HCc 32
#define TKc 32
#define PREDc 12
#define LAMc 0.3f
#define EPSc 1e-8f
#define MAXD 64
#define ESTRIDE 24   // padded edge member list stride (int4-aligned)

typedef unsigned long long u64;

// ---------------- scratch (device globals; no allocation) ----------------
__device__ int   g_edge_nodes[Ec * ESTRIDE];
__device__ int   g_edge_cnt[Ec];
__device__ int   g_node_edges[Nc * MAXD];
__device__ int   g_node_deg[Nc];
__device__ float g_feat[Bc * Nc * 16];
__device__ float g_msum[Bc * Ec];
__device__ float g_Wd[Bc * Ec];
__device__ float g_dvi[Bc * Nc];
__device__ float g_xp[Bc * Tc * Nc * DMc];     // projected node features
__device__ float g_u[Bc * Tc * Ec * DMc];      // edge features (scaled)
__device__ u64   g_zx01[Bc * Nc * Tc * 32];    // precomputed x@wx+b, gates (i,f) packed f32x2
__device__ u64   g_zx23[Bc * Nc * Tc * 32];    // gates (g,o)

// ---------------- math helpers ----------------
__device__ __forceinline__ float sigmf(float x) { return __fdividef(1.f, 1.f + __expf(-x)); }
__device__ __forceinline__ float tanhf_(float x) { return 2.f * sigmf(2.f * x) - 1.f; }
__device__ __forceinline__ float siluf(float x) { return x * sigmf(x); }

__device__ __forceinline__ u64 pack11(float x) {
    u64 r; asm("mov.b64 %0, {%1, %1};" : "=l"(r) : "f"(x)); return r;
}
__device__ __forceinline__ u64 packab(float a, float b) {
    u64 r; asm("mov.b64 %0, {%1, %2};" : "=l"(r) : "f"(a), "f"(b)); return r;
}
__device__ __forceinline__ void ffma2(u64& d, u64 a, u64 b) {
    asm("fma.rn.f32x2 %0, %1, %2, %0;" : "+l"(d) : "l"(a), "l"(b));
}
__device__ __forceinline__ float2 unpk(u64 v) {
    float2 f; asm("mov.b64 {%0, %1}, %2;" : "=f"(f.x), "=f"(f.y) : "l"(v)); return f;
}

// ---------------- adjacency build ----------------
__global__ void k_zero_deg() {
    int i = blockIdx.x * blockDim.x + threadIdx.x;
    if (i < Nc) g_node_deg[i] = 0;
}

__global__ void k_build_edges(const int* __restrict__ members,
                              const int* __restrict__ centers,
                              const int* __restrict__ offsets) {
    int e = blockIdx.x * blockDim.x + threadIdx.x;
    if (e >= Ec) return;
    int s = offsets[e], t = offsets[e + 1];
    int list[ESTRIDE];
    int cnt = 0;
    for (int m = s; m < t && cnt < ESTRIDE; m++) {
        int n = members[m];
        bool dup = false;
        for (int k = 0; k < cnt; k++) if (list[k] == n) { dup = true; break; }
        if (!dup) list[cnt++] = n;
    }
    {
        int c = centers[e];
        bool dup = false;
        for (int k = 0; k < cnt; k++) if (list[k] == c) { dup = true; break; }
        if (!dup && cnt < ESTRIDE) list[cnt++] = c;
    }
    g_edge_cnt[e] = cnt;
    for (int k = 0; k < cnt; k++) {
        int n = list[k];
        g_edge_nodes[e * ESTRIDE + k] = n;
        int pos = atomicAdd(&g_node_deg[n], 1);
        if (pos < MAXD) g_node_edges[n * MAXD + pos] = e;
    }
    for (int k = cnt; k < ESTRIDE; k++) g_edge_nodes[e * ESTRIDE + k] = Nc;  // dummy zero row
}

__global__ void k_sort_nodes() {
    int n = blockIdx.x * blockDim.x + threadIdx.x;
    if (n >= Nc) return;
    int d = g_node_deg[n];
    if (d > MAXD) d = MAXD;
    g_node_deg[n] = d;
    int* L = g_node_edges + n * MAXD;
    for (int i = 1; i < d; i++) {
        int key = L[i];
        int j = i - 1;
        while (j >= 0 && L[j] > key) { L[j + 1] = L[j]; j--; }
        L[j + 1] = key;
    }
    int d8 = (d + 7) & ~7;
    if (d8 > MAXD) d8 = MAXD;
    for (int i = d; i < d8; i++) L[i] = Ec;  // dummy zero row
}

// ---------------- dynamic features: mean/std over T ----------------
__global__ void k_feat(const float* __restrict__ xraw) {
    int idx = blockIdx.x * blockDim.x + threadIdx.x;
    if (idx >= Bc * Nc * C_RAWc) return;
    int c = idx % C_RAWc;
    int n = (idx / C_RAWc) % Nc;
    int b = idx / (C_RAWc * Nc);
    float s1 = 0.f, s2 = 0.f;
    #pragma unroll
    for (int t = 0; t < Tc; t++) {
        float v = xraw[((b * Tc + t) * Nc + n) * C_RAWc + c];
        s1 += v; s2 += v * v;
    }
    float mean = s1 * (1.f / Tc);
    float var = s2 * (1.f / Tc) - mean * mean;
    if (var < 0.f) var = 0.f;
    g_feat[(b * Nc + n) * 16 + c] = mean;
    g_feat[(b * Nc + n) * 16 + C_RAWc + c] = sqrtf(var);
}

// ---------------- per-edge mean similarity (warp per (b,e)) ----------------
__global__ void k_sim(const int* __restrict__ members,
                      const int* __restrict__ centers,
                      const int* __restrict__ offsets) {
    int gid = blockIdx.x * (blockDim.x >> 5) + (threadIdx.x >> 5);
    if (gid >= Bc * Ec) return;
    int e = gid % Ec;
    int b = gid / Ec;
    int lane = threadIdx.x & 31;
    int s = offsets[e];
    int cntm = offsets[e + 1] - s;
    int cn = centers[e];
    const float4* cf4 = (const float4*)(g_feat + (b * Nc + cn) * 16);
    float4 c0 = cf4[0], c1 = cf4[1], c2 = cf4[2], c3 = cf4[3];
    float cn2 = c0.x*c0.x + c0.y*c0.y + c0.z*c0.z + c0.w*c0.w
              + c1.x*c1.x + c1.y*c1.y + c1.z*c1.z + c1.w*c1.w
              + c2.x*c2.x + c2.y*c2.y + c2.z*c2.z + c2.w*c2.w
              + c3.x*c3.x + c3.y*c3.y + c3.z*c3.z + c3.w*c3.w;
    float cnorm = sqrtf(cn2);
    float acc = 0.f;
    for (int m = lane; m < cntm; m += 32) {
        int n = members[s + m];
        const float4* mf4 = (const float4*)(g_feat + (b * Nc + n) * 16);
        float4 m0 = mf4[0], m1 = mf4[1], m2 = mf4[2], m3 = mf4[3];
        float dot = m0.x*c0.x + m0.y*c0.y + m0.z*c0.z + m0.w*c0.w
                  + m1.x*c1.x + m1.y*c1.y + m1.z*c1.z + m1.w*c1.w
                  + m2.x*c2.x + m2.y*c2.y + m2.z*c2.z + m2.w*c2.w
                  + m3.x*c3.x + m3.y*c3.y + m3.z*c3.z + m3.w*c3.w;
        float mn2 = m0.x*m0.x + m0.y*m0.y + m0.z*m0.z + m0.w*m0.w
                  + m1.x*m1.x + m1.y*m1.y + m1.z*m1.z + m1.w*m1.w
                  + m2.x*m2.x + m2.y*m2.y + m2.z*m2.z + m2.w*m2.w
                  + m3.x*m3.x + m3.y*m3.y + m3.z*m3.z + m3.w*m3.w;
        float sim = dot / (sqrtf(mn2) * cnorm + EPSc);
        acc += fminf(fmaxf(sim, 0.f), 1.f);
    }
    #pragma unroll
    for (int o = 16; o > 0; o >>= 1) acc += __shfl_xor_sync(FULLMASK, acc, o);
    if (lane == 0) {
        float count = (float)cntm;
        if (count < 1.f) count = 1.f;
        g_msum[b * Ec + e] = acc / count;
    }
}

// ---------------- per-batch min-max normalize -> Wd ----------------
__global__ void k_wd(const float* __restrict__ W) {
    int b = blockIdx.x;
    int tid = threadIdx.x;
    __shared__ float rmn[256], rmx[256];
    float mn = 1e30f, mx = -1e30f;
    for (int e = tid; e < Ec; e += 256) {
        float v = g_msum[b * Ec + e];
        mn = fminf(mn, v); mx = fmaxf(mx, v);
    }
    rmn[tid] = mn; rmx[tid] = mx;
    __syncthreads();
    for (int s = 128; s > 0; s >>= 1) {
        if (tid < s) {
            rmn[tid] = fminf(rmn[tid], rmn[tid + s]);
            rmx[tid] = fmaxf(rmx[tid], rmx[tid + s]);
        }
        __syncthreads();
    }
    mn = rmn[0]; mx = rmx[0];
    float inv = __fdividef(1.f, mx - mn + EPSc);
    for (int e = tid; e < Ec; e += 256) {
        float v = (g_msum[b * Ec + e] - mn) * inv;
        g_Wd[b * Ec + e] = W[e] * (1.f + LAMc * v);
    }
}

// ---------------- node degree weights -> dvi (warp per (b,n)) ----------------
__global__ void k_dvi() {
    int gid = blockIdx.x * (blockDim.x >> 5) + (threadIdx.x >> 5);
    if (gid >= Bc * Nc) return;
    int n = gid % Nc;
    int b = gid / Nc;
    int lane = threadIdx.x & 31;
    int d = g_node_deg[n];
    float s = 0.f;
    for (int i = lane; i < d; i += 32)
        s += g_Wd[b * Ec + g_node_edges[n * MAXD + i]];
    #pragma unroll
    for (int o = 16; o > 0; o >>= 1) s += __shfl_xor_sync(FULLMASK, s, o);
    if (lane == 0) g_dvi[gid] = rsqrtf(fmaxf(s, EPSc));
}

// ---------------- input projection ----------------
__global__ void k_xp(const float* __restrict__ x,
                     const float* __restrict__ w,
                     const float* __restrict__ bias) {
    int idx = blockIdx.x * blockDim.x + threadIdx.x;
    if (idx >= Bc * Tc * Nc * DMc) return;
    int j = idx & 31;
    int row = idx >> 5;
    float acc = bias[j];
    #pragma unroll
    for (int k = 0; k < F_INc; k++) acc += x[row * F_INc + k] * w[k * DMc + j];
    g_xp[idx] = acc;
}

// ---------------- edge gather: u = (Wd/De) * H^T (dvi*xp) ----------------
__global__ __launch_bounds__(512) void k_edge_gather() {
    extern __shared__ float xs[];  // (Nc+1)*32 floats
    int bt = blockIdx.x >> 1;
    int part = blockIdx.x & 1;
    int b = bt / Tc;
    const float4* xp4 = (const float4*)(g_xp + (size_t)bt * Nc * DMc);
    float4* xs4 = (float4*)xs;
    for (int i = threadIdx.x; i < (Nc + 1) * 8; i += blockDim.x) {
        if (i < Nc * 8) {
            int n = i >> 3;
            float d = g_dvi[b * Nc + n];
            float4 v = xp4[i];
            v.x *= d; v.y *= d; v.z *= d; v.w *= d;
            xs4[i] = v;
        } else {
            xs4[i] = make_float4(0.f, 0.f, 0.f, 0.f);
        }
    }
    __syncthreads();
    int lane = threadIdx.x & 31;
    int w = threadIdx.x >> 5;
    int e0 = part * (Ec / 2), e1 = e0 + (Ec / 2);
    for (int e = e0 + w; e < e1; e += 16) {
        int cnt = g_edge_cnt[e];
        const int4* ip = (const int4*)(g_edge_nodes + e * ESTRIDE);
        int4 v0 = ip[0], v1 = ip[1], v2 = ip[2], v3 = ip[3], v4 = ip[4], v5 = ip[5];
        int idx[ESTRIDE] = {v0.x, v0.y, v0.z, v0.w, v1.x, v1.y, v1.z, v1.w,
                            v2.x, v2.y, v2.z, v2.w, v3.x, v3.y, v3.z, v3.w,
                            v4.x, v4.y, v4.z, v4.w, v5.x, v5.y, v5.z, v5.w};
        float acc = 0.f;
        #pragma unroll
        for (int k = 0; k < ESTRIDE; k++) acc += xs[idx[k] * DMc + lane];
        float sc = __fdividef(g_Wd[b * Ec + e], (float)cnt);
        g_u[((size_t)bt * Ec + e) * DMc + lane] = acc * sc;
    }
}

// ---------------- node gather + conv + silu + fused zx = h@wx + b ----------------
// dyn smem layout (ull first for alignment):
//   swx01[1024] u64 | swx23[1024] u64 | sb01[32] u64 | sb23[32] u64 |
//   us[(Ec+1)*32] f32 | cw[1024] f32 | cb[32] f32
__global__ __launch_bounds__(512) void k_node_conv(
    const float* __restrict__ conv_w, const float* __restrict__ conv_b,
    const float* __restrict__ wx, const float* __restrict__ lb) {
    extern __shared__ __align__(16) char smraw[];
    u64*   swx01 = (u64*)smraw;
    u64*   swx23 = swx01 + 1024;
    u64*   sb01  = swx23 + 1024;
    u64*   sb23  = sb01 + 32;
    float* us    = (float*)(sb23 + 32);
    float* cw    = us + (Ec + 1) * DMc;
    float* cb    = cw + DMc * HCc;

    int bt = blockIdx.x >> 1;
    int part = blockIdx.x & 1;
    int b = bt / Tc;
    int t = bt % Tc;

    const float4* u4 = (const float4*)(g_u + (size_t)bt * Ec * DMc);
    float4* us4 = (float4*)us;
    for (int i = threadIdx.x; i < (Ec + 1) * 8; i += blockDim.x)
        us4[i] = (i < Ec * 8) ? u4[i] : make_float4(0.f, 0.f, 0.f, 0.f);
    for (int i = threadIdx.x; i < DMc * HCc; i += blockDim.x) {
        cw[i] = conv_w[i];
        int r = i >> 5, l = i & 31;
        swx01[i] = packab(wx[r * 128 + l], wx[r * 128 + 32 + l]);
        swx23[i] = packab(wx[r * 128 + 64 + l], wx[r * 128 + 96 + l]);
    }
    if (threadIdx.x < HCc) {
        int l = threadIdx.x;
        cb[l] = conv_b[l];
        sb01[l] = packab(lb[l], lb[32 + l]);
        sb23[l] = packab(lb[64 + l], lb[96 + l]);
    }
    __syncthreads();

    int lane = threadIdx.x & 31;
    int w = threadIdx.x >> 5;
    int n0 = part * (Nc / 2), n1 = n0 + (Nc / 2);
    for (int n = n0 + w; n < n1; n += 16) {
        int deg = g_node_deg[n];
        int d8 = (deg + 7) & ~7;
        float acc = 0.f;
        const int* L = g_node_edges + n * MAXD;
        for (int k0 = 0; k0 < d8; k0 += 8) {
            const int4* ip = (const int4*)(L + k0);
            int4 a = ip[0], bb = ip[1];
            acc += us[a.x * DMc + lane];
            acc += us[a.y * DMc + lane];
            acc += us[a.z * DMc + lane];
            acc += us[a.w * DMc + lane];
            acc += us[bb.x * DMc + lane];
            acc += us[bb.y * DMc + lane];
            acc += us[bb.z * DMc + lane];
            acc += us[bb.w * DMc + lane];
        }
        acc *= g_dvi[b * Nc + n];
        // conv 32x32 via shuffles
        float z = cb[lane];
        #pragma unroll 8
        for (int f = 0; f < DMc; f++) {
            float af = __shfl_sync(FULLMASK, acc, f);
            z += af * cw[f * HCc + lane];
        }
        float hval = siluf(z);
        // zx = hval @ wx + lb, packed gate pairs
        u64 a01 = sb01[lane], a23 = sb23[lane];
        #pragma unroll 8
        for (int i = 0; i < HCc; i++) {
            float hi = __shfl_sync(FULLMASK, hval, i);
            u64 hi2 = pack11(hi);
            ffma2(a01, hi2, swx01[i * 32 + lane]);
            ffma2(a23, hi2, swx23[i * 32 + lane]);
        }
        size_t o = ((size_t)(b * Nc + n) * Tc + t) * 32 + lane;
        g_zx01[o] = a01;
        g_zx23[o] = a23;
    }
}

// ---------------- LSTM recurrence (h@wh only, f32x2) + head ----------------
__global__ __launch_bounds__(256) void k_lstm(
    const float* __restrict__ wh,
    const float* __restrict__ hw1, const float* __restrict__ hb1,
    const float* __restrict__ hw2, const float* __restrict__ hb2,
    float* __restrict__ out, int Pout) {
    __shared__ u64 swh01[1024];
    __shared__ u64 swh23[1024];
    __shared__ float hw1s[1024];
    __shared__ float hb1s[32];
    __shared__ float hw2s[32 * PREDc];
    __shared__ float hb2s[PREDc];

    for (int idx = threadIdx.x; idx < 1024; idx += 256) {
        int i = idx >> 5, l = idx & 31;
        swh01[idx] = packab(wh[i * 128 + l], wh[i * 128 + 32 + l]);
        swh23[idx] = packab(wh[i * 128 + 64 + l], wh[i * 128 + 96 + l]);
        hw1s[idx] = hw1[idx];
    }
    if (threadIdx.x < 32) hb1s[threadIdx.x] = hb1[threadIdx.x];
    for (int idx = threadIdx.x; idx < 32 * PREDc; idx += 256) hw2s[idx] = hw2[idx];
    if (threadIdx.x < PREDc) hb2s[threadIdx.x] = hb2[threadIdx.x];
    __syncthreads();

    int lane = threadIdx.x & 31;
    int w = threadIdx.x >> 5;
    int rowbase = (blockIdx.x * 8 + w) * 8;

    float h[8], c[8];
    #pragma unroll
    for (int r = 0; r < 8; r++) { h[r] = 0.f; c[r] = 0.f; }

    for (int t = 0; t < Tc; t++) {
        u64 z01[8], z23[8];
        #pragma unroll
        for (int r = 0; r < 8; r++) {
            size_t o = ((size_t)(rowbase + r) * Tc + t) * 32 + lane;
            z01[r] = g_zx01[o];
            z23[r] = g_zx23[o];
        }
        #pragma unroll 4
        for (int i = 0; i < 32; i++) {
            u64 w01 = swh01[i * 32 + lane];
            u64 w23 = swh23[i * 32 + lane];
            #pragma unroll
            for (int r = 0; r < 8; r++) {
                float hi = __shfl_sync(FULLMASK, h[r], i);
                u64 hi2 = pack11(hi);
                ffma2(z01[r], hi2, w01);
                ffma2(z23[r], hi2, w23);
            }
        }
        #pragma unroll
        for (int r = 0; r < 8; r++) {
            float2 zif = unpk(z01[r]);
            float2 zgo = unpk(z23[r]);
            float ig = sigmf(zif.x);
            float fg = sigmf(zif.y);
            float gg = tanhf_(zgo.x);
            float og = sigmf(zgo.y);
            c[r] = fg * c[r] + ig * gg;
            h[r] = og * tanhf_(c[r]);
        }
    }

    // head: y = silu(h @ hw1 + hb1) @ hw2 + hb2
    #pragma unroll
    for (int r = 0; r < 8; r++) {
        int row = rowbase + r;
        int b = row / Nc;
        int n = row % Nc;
        float a = hb1s[lane];
        #pragma unroll 8
        for (int i = 0; i < 32; i++) {
            float hi = __shfl_sync(FULLMASK, h[r], i);
            a += hi * hw1s[i * 32 + lane];
        }
        float y1 = siluf(a);
        float o = (lane < PREDc) ? hb2s[lane] : 0.f;
        #pragma unroll 8
        for (int j = 0; j < 32; j++) {
            float yj = __shfl_sync(FULLMASK, y1, j);
            if (lane < PREDc) o += yj * hw2s[j * PREDc + lane];
        }
        if (lane < Pout) out[((size_t)b * Pout + lane) * Nc + n] = o;
    }
}

// ---------------- launch ----------------
extern "C" void kernel_launch(void* const* d_in, const int* in_sizes, int n_in,
                              void* d_out, int out_size) {
    const float* x       = (const float*)d_in[0];
    const float* xraw    = (const float*)d_in[1];
    const float* W       = (const float*)d_in[3];
    const int*   members = (const int*)d_in[4];
    const int*   centers = (const int*)d_in[5];
    const int*   offsets = (const int*)d_in[6];
    const float* ipw     = (const float*)d_in[7];
    const float* ipb     = (const float*)d_in[8];
    const float* cw      = (const float*)d_in[9];
    const float* cb      = (const float*)d_in[10];
    const float* wx      = (const float*)d_in[11];
    const float* wh      = (const float*)d_in[12];
    const float* lb      = (const float*)d_in[13];
    const float* hw1     = (const float*)d_in[14];
    const float* hb1     = (const float*)d_in[15];
    const float* hw2     = (const float*)d_in[16];
    const float* hb2     = (const float*)d_in[17];
    float* out = (float*)d_out;
    int Pout = out_size / (Bc * Nc);

    int smem_edge = (Nc + 1) * DMc * sizeof(float);  // 128128
    int smem_node = (2112) * sizeof(u64) + ((Ec + 1) * DMc + DMc * HCc + HCc) * sizeof(float);
    cudaFuncSetAttribute(k_edge_gather, cudaFuncAttributeMaxDynamicSharedMemorySize, smem_edge);
    cudaFuncSetAttribute(k_node_conv, cudaFuncAttributeMaxDynamicSharedMemorySize, smem_node);

    k_zero_deg<<<4, 256>>>();
    k_build_edges<<<4, 256>>>(members, centers, offsets);
    k_sort_nodes<<<4, 256>>>();
    k_feat<<<(Bc * Nc * C_RAWc + 255) / 256, 256>>>(xraw);
    k_sim<<<(Bc * Ec + 7) / 8, 256>>>(members, centers, offsets);
    k_wd<<<Bc, 256>>>(W);
    k_dvi<<<(Bc * Nc + 7) / 8, 256>>>();
    k_xp<<<(Bc * Tc * Nc * DMc + 255) / 256, 256>>>(x, ipw, ipb);
    k_edge_gather<<<Bc * Tc * 2, 512, smem_edge>>>();
    k_node_conv<<<Bc * Tc * 2, 512, smem_node>>>(cw, cb, wx, lb);
    k_lstm<<<Bc * Nc / 64, 256>>>(wh, hw1, hb1, hw2, hb2, out, Pout);
}

// round 3
// speedup vs baseline: 1.3612x; 1.1641x over previous
#include <cuda_runtime.h>
#include <math.h>

#define FULLMASK 0xffffffffu

#define Bc 8
#define Tc 24
#define Nc 1000
#define Ec 1000
#define F_INc 16
#define C_RAWc 8
#define DMc 32
#define HCc 32
#define PREDc 12
#define LAMc 0.3f
#define EPSc 1e-8f
#define MAXD 64
#define ESTRIDE 24     // padded edge member list stride (int4-aligned)
#define USH 15         // g_u slice shift: 1024 rows * 32 floats

typedef unsigned long long u64;

// ---------------- scratch (device globals; no allocation) ----------------
__device__ int   g_edge_nodes[Ec * ESTRIDE];
__device__ int   g_edge_cnt[Ec];
__device__ int   g_node_edges[Nc * MAXD];
__device__ int   g_node_deg[Nc];
__device__ float g_feat[Bc * Nc * 16];
__device__ float g_msum[Bc * Ec];
__device__ float g_Wd[Bc * Ec];
__device__ float g_dvi[Bc * Nc];
__device__ float g_u[(size_t)Bc * Tc * 1024 * DMc];  // edge features, 1024-row slices

// ---------------- math helpers ----------------
__device__ __forceinline__ float sigmf(float x) { return __fdividef(1.f, 1.f + __expf(-x)); }
__device__ __forceinline__ float tanhf_(float x) { return 2.f * sigmf(2.f * x) - 1.f; }
__device__ __forceinline__ float siluf(float x) { return x * sigmf(x); }

__device__ __forceinline__ u64 pack11(float x) {
    u64 r; asm("mov.b64 %0, {%1, %1};" : "=l"(r) : "f"(x)); return r;
}
__device__ __forceinline__ u64 packab(float a, float b) {
    u64 r; asm("mov.b64 %0, {%1, %2};" : "=l"(r) : "f"(a), "f"(b)); return r;
}
__device__ __forceinline__ void ffma2(u64& d, u64 a, u64 b) {
    asm("fma.rn.f32x2 %0, %1, %2, %0;" : "+l"(d) : "l"(a), "l"(b));
}
__device__ __forceinline__ float2 unpk(u64 v) {
    float2 f; asm("mov.b64 {%0, %1}, %2;" : "=f"(f.x), "=f"(f.y) : "l"(v)); return f;
}

// ---------------- adjacency build ----------------
__global__ void k_zero_deg() {
    int i = blockIdx.x * blockDim.x + threadIdx.x;
    if (i < Nc) g_node_deg[i] = 0;
}

__global__ void k_build_edges(const int* __restrict__ members,
                              const int* __restrict__ centers,
                              const int* __restrict__ offsets) {
    int e = blockIdx.x * blockDim.x + threadIdx.x;
    if (e >= Ec) return;
    int s = offsets[e], t = offsets[e + 1];
    int list[ESTRIDE];
    int cnt = 0;
    for (int m = s; m < t && cnt < ESTRIDE; m++) {
        int n = members[m];
        bool dup = false;
        for (int k = 0; k < cnt; k++) if (list[k] == n) { dup = true; break; }
        if (!dup) list[cnt++] = n;
    }
    {
        int c = centers[e];
        bool dup = false;
        for (int k = 0; k < cnt; k++) if (list[k] == c) { dup = true; break; }
        if (!dup && cnt < ESTRIDE) list[cnt++] = c;
    }
    g_edge_cnt[e] = cnt;
    for (int k = 0; k < cnt; k++) {
        int n = list[k];
        g_edge_nodes[e * ESTRIDE + k] = n;
        int pos = atomicAdd(&g_node_deg[n], 1);
        if (pos < MAXD) g_node_edges[n * MAXD + pos] = e;
    }
    for (int k = cnt; k < ESTRIDE; k++) g_edge_nodes[e * ESTRIDE + k] = Nc;  // dummy zero row in xs
}

__global__ void k_sort_nodes() {
    int n = blockIdx.x * blockDim.x + threadIdx.x;
    if (n >= Nc) return;
    int d = g_node_deg[n];
    if (d > MAXD) d = MAXD;
    g_node_deg[n] = d;
    int* L = g_node_edges + n * MAXD;
    for (int i = 1; i < d; i++) {
        int key = L[i];
        int j = i - 1;
        while (j >= 0 && L[j] > key) { L[j + 1] = L[j]; j--; }
        L[j + 1] = key;
    }
    int d8 = (d + 7) & ~7;
    if (d8 > MAXD) d8 = MAXD;
    for (int i = d; i < d8; i++) L[i] = Ec;  // dummy: g_u row 1000 is zeroed
}

// ---------------- dynamic features: mean/std over T ----------------
__global__ void k_feat(const float* __restrict__ xraw) {
    int idx = blockIdx.x * blockDim.x + threadIdx.x;
    if (idx >= Bc * Nc * C_RAWc) return;
    int c = idx % C_RAWc;
    int n = (idx / C_RAWc) % Nc;
    int b = idx / (C_RAWc * Nc);
    float s1 = 0.f, s2 = 0.f;
    #pragma unroll
    for (int t = 0; t < Tc; t++) {
        float v = xraw[((b * Tc + t) * Nc + n) * C_RAWc + c];
        s1 += v; s2 += v * v;
    }
    float mean = s1 * (1.f / Tc);
    float var = s2 * (1.f / Tc) - mean * mean;
    if (var < 0.f) var = 0.f;
    g_feat[(b * Nc + n) * 16 + c] = mean;
    g_feat[(b * Nc + n) * 16 + C_RAWc + c] = sqrtf(var);
}

// ---------------- per-edge mean similarity (warp per (b,e)) ----------------
__global__ void k_sim(const int* __restrict__ members,
                      const int* __restrict__ centers,
                      const int* __restrict__ offsets) {
    int gid = blockIdx.x * (blockDim.x >> 5) + (threadIdx.x >> 5);
    if (gid >= Bc * Ec) return;
    int e = gid % Ec;
    int b = gid / Ec;
    int lane = threadIdx.x & 31;
    int s = offsets[e];
    int cntm = offsets[e + 1] - s;
    int cn = centers[e];
    const float4* cf4 = (const float4*)(g_feat + (b * Nc + cn) * 16);
    float4 c0 = cf4[0], c1 = cf4[1], c2 = cf4[2], c3 = cf4[3];
    float cn2 = c0.x*c0.x + c0.y*c0.y + c0.z*c0.z + c0.w*c0.w
              + c1.x*c1.x + c1.y*c1.y + c1.z*c1.z + c1.w*c1.w
              + c2.x*c2.x + c2.y*c2.y + c2.z*c2.z + c2.w*c2.w
              + c3.x*c3.x + c3.y*c3.y + c3.z*c3.z + c3.w*c3.w;
    float cnorm = sqrtf(cn2);
    float acc = 0.f;
    for (int m = lane; m < cntm; m += 32) {
        int n = members[s + m];
        const float4* mf4 = (const float4*)(g_feat + (b * Nc + n) * 16);
        float4 m0 = mf4[0], m1 = mf4[1], m2 = mf4[2], m3 = mf4[3];
        float dot = m0.x*c0.x + m0.y*c0.y + m0.z*c0.z + m0.w*c0.w
                  + m1.x*c1.x + m1.y*c1.y + m1.z*c1.z + m1.w*c1.w
                  + m2.x*c2.x + m2.y*c2.y + m2.z*c2.z + m2.w*c2.w
                  + m3.x*c3.x + m3.y*c3.y + m3.z*c3.z + m3.w*c3.w;
        float mn2 = m0.x*m0.x + m0.y*m0.y + m0.z*m0.z + m0.w*m0.w
                  + m1.x*m1.x + m1.y*m1.y + m1.z*m1.z + m1.w*m1.w
                  + m2.x*m2.x + m2.y*m2.y + m2.z*m2.z + m2.w*m2.w
                  + m3.x*m3.x + m3.y*m3.y + m3.z*m3.z + m3.w*m3.w;
        float sim = dot / (sqrtf(mn2) * cnorm + EPSc);
        acc += fminf(fmaxf(sim, 0.f), 1.f);
    }
    #pragma unroll
    for (int o = 16; o > 0; o >>= 1) acc += __shfl_xor_sync(FULLMASK, acc, o);
    if (lane == 0) {
        float count = (float)cntm;
        if (count < 1.f) count = 1.f;
        g_msum[b * Ec + e] = acc / count;
    }
}

// ---------------- per-batch min-max normalize -> Wd ----------------
__global__ void k_wd(const float* __restrict__ W) {
    int b = blockIdx.x;
    int tid = threadIdx.x;
    __shared__ float rmn[256], rmx[256];
    float mn = 1e30f, mx = -1e30f;
    for (int e = tid; e < Ec; e += 256) {
        float v = g_msum[b * Ec + e];
        mn = fminf(mn, v); mx = fmaxf(mx, v);
    }
    rmn[tid] = mn; rmx[tid] = mx;
    __syncthreads();
    for (int s = 128; s > 0; s >>= 1) {
        if (tid < s) {
            rmn[tid] = fminf(rmn[tid], rmn[tid + s]);
            rmx[tid] = fmaxf(rmx[tid], rmx[tid + s]);
        }
        __syncthreads();
    }
    mn = rmn[0]; mx = rmx[0];
    float inv = __fdividef(1.f, mx - mn + EPSc);
    for (int e = tid; e < Ec; e += 256) {
        float v = (g_msum[b * Ec + e] - mn) * inv;
        g_Wd[b * Ec + e] = W[e] * (1.f + LAMc * v);
    }
}

// ---------------- node degree weights -> dvi (warp per (b,n)) ----------------
__global__ void k_dvi() {
    int gid = blockIdx.x * (blockDim.x >> 5) + (threadIdx.x >> 5);
    if (gid >= Bc * Nc) return;
    int n = gid % Nc;
    int b = gid / Nc;
    int lane = threadIdx.x & 31;
    int d = g_node_deg[n];
    float s = 0.f;
    for (int i = lane; i < d; i += 32)
        s += g_Wd[b * Ec + g_node_edges[n * MAXD + i]];
    #pragma unroll
    for (int o = 16; o > 0; o >>= 1) s += __shfl_xor_sync(FULLMASK, s, o);
    if (lane == 0) g_dvi[gid] = rsqrtf(fmaxf(s, EPSc));
}

// ---------------- edge gather (+ fused input projection) ----------------
// block per ((b,t), half-of-edges): stage dvi*(x@ipw+ipb) into smem, gather edges -> g_u
__global__ __launch_bounds__(512) void k_edge_gather(const float* __restrict__ x,
                                                     const float* __restrict__ ipw,
                                                     const float* __restrict__ ipb) {
    extern __shared__ float xs[];            // (Nc+1)*32
    float* sipw = xs + (Nc + 1) * 32;        // 512
    float* sipb = sipw + 512;                // 32
    int bt = blockIdx.x >> 1;
    int part = blockIdx.x & 1;
    int b = bt / Tc;

    if (threadIdx.x < 512) sipw[threadIdx.x] = ipw[threadIdx.x];
    if (threadIdx.x < 32) sipb[threadIdx.x] = ipb[threadIdx.x];
    __syncthreads();

    const float* xb = x + (size_t)bt * Nc * F_INc;
    float4* xs4 = (float4*)xs;
    for (int i = threadIdx.x; i < (Nc + 1) * 8; i += 512) {
        int n = i >> 3, q = (i & 7) * 4;
        float4 v = make_float4(0.f, 0.f, 0.f, 0.f);
        if (n < Nc) {
            const float* xr = xb + n * F_INc;
            float a0 = sipb[q], a1 = sipb[q + 1], a2 = sipb[q + 2], a3 = sipb[q + 3];
            #pragma unroll
            for (int k = 0; k < F_INc; k++) {
                float xv = xr[k];
                a0 += xv * sipw[k * 32 + q];
                a1 += xv * sipw[k * 32 + q + 1];
                a2 += xv * sipw[k * 32 + q + 2];
                a3 += xv * sipw[k * 32 + q + 3];
            }
            float d = g_dvi[b * Nc + n];
            v = make_float4(a0 * d, a1 * d, a2 * d, a3 * d);
        }
        xs4[i] = v;
    }
    __syncthreads();

    int lane = threadIdx.x & 31;
    int w = threadIdx.x >> 5;
    float* ub = g_u + ((size_t)bt << USH);
    int e0 = part * (Ec / 2);
    for (int e = e0 + w; e < e0 + Ec / 2; e += 16) {
        int cnt = g_edge_cnt[e];
        const int4* ip = (const int4*)(g_edge_nodes + e * ESTRIDE);
        int4 v0 = ip[0], v1 = ip[1], v2 = ip[2], v3 = ip[3], v4 = ip[4], v5 = ip[5];
        int idx[ESTRIDE] = {v0.x, v0.y, v0.z, v0.w, v1.x, v1.y, v1.z, v1.w,
                            v2.x, v2.y, v2.z, v2.w, v3.x, v3.y, v3.z, v3.w,
                            v4.x, v4.y, v4.z, v4.w, v5.x, v5.y, v5.z, v5.w};
        float acc = 0.f;
        #pragma unroll
        for (int k = 0; k < ESTRIDE; k++) acc += xs[idx[k] * DMc + lane];
        float sc = __fdividef(g_Wd[b * Ec + e], (float)cnt);
        ub[(e << 5) + lane] = acc * sc;
    }
    if (part) {  // zero pad rows 1000..1023 (dummy gather target)
        for (int e = Ec + w; e < 1024; e += 16) ub[(e << 5) + lane] = 0.f;
    }
}

// ---------------- fully fused: node gather + conv + [hc;h]@[wx;wh] + LSTM + head ----------------
// block = 4 warps x 8 nodes = 32 rows; per t: gather from g_u (L2), conv, combined gemm, step.
__global__ __launch_bounds__(128) void k_fused(
    const float* __restrict__ wx, const float* __restrict__ wh,
    const float* __restrict__ lb,
    const float* __restrict__ cwg, const float* __restrict__ cbg,
    const float* __restrict__ hw1, const float* __restrict__ hb1,
    const float* __restrict__ hw2, const float* __restrict__ hb2,
    float* __restrict__ out, int Pout) {
    extern __shared__ __align__(16) char smr[];
    u64*   sw01 = (u64*)smr;           // 2048: combined [wx;wh] gate pair (0,1)
    u64*   sw23 = sw01 + 2048;         // 2048: gate pair (2,3)
    u64*   sb01 = sw23 + 2048;         // 32
    u64*   sb23 = sb01 + 32;           // 32
    u64*   hb   = sb23 + 32;           // 4 warps * 8 rows * 64 slots
    float* cwS  = (float*)(hb + 2048); // 1024
    float* cbS  = cwS + 1024;          // 32
    float* hw1S = cbS + 32;            // 1024
    float* hb1S = hw1S + 1024;         // 32
    float* hw2S = hb1S + 32;           // 384
    float* hb2S = hw2S + 384;          // 16
    float* sdvi = hb2S + 16;           // 32
    int*   sidx = (int*)(sdvi + 32);   // 32*64
    int*   sdeg = sidx + 2048;         // 32

    int tid = threadIdx.x;
    int rb = blockIdx.x * 32;

    for (int idx = tid; idx < 2048; idx += 128) {
        int i = idx >> 5, l = idx & 31;
        const float* src = (i < 32) ? (wx + i * 128) : (wh + (i - 32) * 128);
        sw01[idx] = packab(src[l], src[32 + l]);
        sw23[idx] = packab(src[64 + l], src[96 + l]);
        int row = rb + (idx >> 6);
        sidx[idx] = g_node_edges[(row % Nc) * MAXD + (idx & 63)];
    }
    for (int idx = tid; idx < 1024; idx += 128) { cwS[idx] = cwg[idx]; hw1S[idx] = hw1[idx]; }
    for (int idx = tid; idx < 384; idx += 128) hw2S[idx] = hw2[idx];
    if (tid < 32) {
        sb01[tid] = packab(lb[tid], lb[32 + tid]);
        sb23[tid] = packab(lb[64 + tid], lb[96 + tid]);
        cbS[tid] = cbg[tid];
        hb1S[tid] = hb1[tid];
        if (tid < PREDc) hb2S[tid] = hb2[tid];
        int row = rb + tid;
        int b = row / Nc, n = row % Nc;
        sdvi[tid] = g_dvi[b * Nc + n];
        int d = g_node_deg[n];
        sdeg[tid] = (d + 7) & ~7;
    }
    __syncthreads();

    int lane = tid & 31;
    int w = tid >> 5;
    u64* hbw = hb + w * 512;

    int d8r[8], bTr[8];
    #pragma unroll
    for (int r = 0; r < 8; r++) {
        int local = w * 8 + r;
        d8r[r] = sdeg[local];
        bTr[r] = ((rb + local) / Nc) * Tc;
    }

    float h[8], c[8];
    #pragma unroll
    for (int r = 0; r < 8; r++) { h[r] = 0.f; c[r] = 0.f; }

    for (int t = 0; t < Tc; t++) {
        float hc[8];
        #pragma unroll
        for (int r = 0; r < 8; r++) {
            const float* up = g_u + ((size_t)(bTr[r] + t) << USH);
            const int* L = sidx + (w * 8 + r) * 64;
            float acc = 0.f;
            for (int k0 = 0; k0 < d8r[r]; k0 += 8) {
                int4 a = *(const int4*)(L + k0);
                int4 b2 = *(const int4*)(L + k0 + 4);
                acc += up[(a.x << 5) + lane] + up[(a.y << 5) + lane]
                     + up[(a.z << 5) + lane] + up[(a.w << 5) + lane]
                     + up[(b2.x << 5) + lane] + up[(b2.y << 5) + lane]
                     + up[(b2.z << 5) + lane] + up[(b2.w << 5) + lane];
            }
            acc *= sdvi[w * 8 + r];
            float z = cbS[lane];
            #pragma unroll 8
            for (int f = 0; f < DMc; f++)
                z += __shfl_sync(FULLMASK, acc, f) * cwS[f * 32 + lane];
            hc[r] = siluf(z);
        }
        __syncwarp();
        #pragma unroll
        for (int r = 0; r < 8; r++) {
            hbw[r * 64 + lane] = pack11(hc[r]);
            hbw[r * 64 + 32 + lane] = pack11(h[r]);
        }
        __syncwarp();
        u64 z01[8], z23[8];
        #pragma unroll
        for (int r = 0; r < 8; r++) { z01[r] = sb01[lane]; z23[r] = sb23[lane]; }
        #pragma unroll 4
        for (int i = 0; i < 64; i++) {
            u64 w01 = sw01[(i << 5) + lane];
            u64 w23 = sw23[(i << 5) + lane];
            #pragma unroll
            for (int r = 0; r < 8; r++) {
                u64 hv = hbw[r * 64 + i];
                ffma2(z01[r], hv, w01);
                ffma2(z23[r], hv, w23);
            }
        }
        #pragma unroll
        for (int r = 0; r < 8; r++) {
            float2 zif = unpk(z01[r]);
            float2 zgo = unpk(z23[r]);
            float ig = sigmf(zif.x);
            float fg = sigmf(zif.y);
            float gg = tanhf_(zgo.x);
            float og = sigmf(zgo.y);
            c[r] = fg * c[r] + ig * gg;
            h[r] = og * tanhf_(c[r]);
        }
    }

    // head: y = silu(h @ hw1 + hb1) @ hw2 + hb2
    #pragma unroll
    for (int r = 0; r < 8; r++) {
        int row = rb + w * 8 + r;
        int b = row / Nc;
        int n = row % Nc;
        float a = hb1S[lane];
        #pragma unroll 8
        for (int i = 0; i < 32; i++) {
            float hi = __shfl_sync(FULLMASK, h[r], i);
            a += hi * hw1S[i * 32 + lane];
        }
        float y1 = siluf(a);
        float o = (lane < PREDc) ? hb2S[lane] : 0.f;
        #pragma unroll 8
        for (int j = 0; j < 32; j++) {
            float yj = __shfl_sync(FULLMASK, y1, j);
            if (lane < PREDc) o += yj * hw2S[j * PREDc + lane];
        }
        if (lane < Pout) out[((size_t)b * Pout + lane) * Nc + n] = o;
    }
}

// ---------------- launch ----------------
extern "C" void kernel_launch(void* const* d_in, const int* in_sizes, int n_in,
                              void* d_out, int out_size) {
    const float* x       = (const float*)d_in[0];
    const float* xraw    = (const float*)d_in[1];
    const float* W       = (const float*)d_in[3];
    const int*   members = (const int*)d_in[4];
    const int*   centers = (const int*)d_in[5];
    const int*   offsets = (const int*)d_in[6];
    const float* ipw     = (const float*)d_in[7];
    const float* ipb     = (const float*)d_in[8];
    const float* cw      = (const float*)d_in[9];
    const float* cb      = (const float*)d_in[10];
    const float* wx      = (const float*)d_in[11];
    const float* wh      = (const float*)d_in[12];
    const float* lb      = (const float*)d_in[13];
    const float* hw1     = (const float*)d_in[14];
    const float* hb1     = (const float*)d_in[15];
    const float* hw2     = (const float*)d_in[16];
    const float* hb2     = (const float*)d_in[17];
    float* out = (float*)d_out;
    int Pout = out_size / (Bc * Nc);

    int smem_edge = ((Nc + 1) * 32 + 512 + 32) * sizeof(float);        // 130304
    int smem_fused = 6208 * sizeof(u64) + 2544 * sizeof(float) + 2080 * sizeof(int);  // 68160
    cudaFuncSetAttribute(k_edge_gather, cudaFuncAttributeMaxDynamicSharedMemorySize, smem_edge);
    cudaFuncSetAttribute(k_fused, cudaFuncAttributeMaxDynamicSharedMemorySize, smem_fused);

    k_zero_deg<<<4, 256>>>();
    k_build_edges<<<4, 256>>>(members, centers, offsets);
    k_sort_nodes<<<4, 256>>>();
    k_feat<<<(Bc * Nc * C_RAWc + 255) / 256, 256>>>(xraw);
    k_sim<<<(Bc * Ec + 7) / 8, 256>>>(members, centers, offsets);
    k_wd<<<Bc, 256>>>(W);
    k_dvi<<<(Bc * Nc + 7) / 8, 256>>>();
    k_edge_gather<<<Bc * Tc * 2, 512, smem_edge>>>(x, ipw, ipb);
    k_fused<<<Bc * Nc / 32, 128, smem_fused>>>(wx, wh, lb, cw, cb,
                                               hw1, hb1, hw2, hb2, out, Pout);
}

// round 4
// speedup vs baseline: 1.5714x; 1.1545x over previous
#include <cuda_runtime.h>
#include <math.h>

#define FULLMASK 0xffffffffu

#define Bc 8
#define Tc 24
#define Nc 1000
#define Ec 1000
#define F_INc 16
#define C_RAWc 8
#define DMc 32
#define HCc 32
#define PREDc 12
#define LAMc 0.3f
#define EPSc 1e-8f
#define MAXD 64
#define ESTRIDE 24     // padded edge member list stride (int4-aligned)
#define USH 15         // g_u slice shift: 1024 rows * 32 floats
#define RPW 4          // rows per warp in k_fused
#define RPB 16         // rows per block (4 warps)

typedef unsigned long long u64;

// ---------------- scratch (device globals; no allocation) ----------------
__device__ int   g_edge_nodes[Ec * ESTRIDE];
__device__ int   g_edge_cnt[Ec];
__device__ int   g_node_edges[Nc * MAXD];
__device__ int   g_node_deg[Nc];
__device__ float g_feat[Bc * Nc * 16];
__device__ float g_msum[Bc * Ec];
__device__ float g_Wd[Bc * Ec];
__device__ float g_dvi[Bc * Nc];
__device__ float g_u[(size_t)Bc * Tc * 1024 * DMc];  // edge features, 1024-row slices

// ---------------- math helpers ----------------
__device__ __forceinline__ float sigmf(float x) { return __fdividef(1.f, 1.f + __expf(-x)); }
__device__ __forceinline__ float tanhf_(float x) { return 2.f * sigmf(2.f * x) - 1.f; }
__device__ __forceinline__ float siluf(float x) { return x * sigmf(x); }

__device__ __forceinline__ u64 pack11(float x) {
    u64 r; asm("mov.b64 %0, {%1, %1};" : "=l"(r) : "f"(x)); return r;
}
__device__ __forceinline__ u64 packab(float a, float b) {
    u64 r; asm("mov.b64 %0, {%1, %2};" : "=l"(r) : "f"(a), "f"(b)); return r;
}
__device__ __forceinline__ void ffma2(u64& d, u64 a, u64 b) {
    asm("fma.rn.f32x2 %0, %1, %2, %0;" : "+l"(d) : "l"(a), "l"(b));
}
__device__ __forceinline__ float2 unpk(u64 v) {
    float2 f; asm("mov.b64 {%0, %1}, %2;" : "=f"(f.x), "=f"(f.y) : "l"(v)); return f;
}

// ---------------- adjacency build ----------------
__global__ void k_zero_deg() {
    int i = blockIdx.x * blockDim.x + threadIdx.x;
    if (i < Nc) g_node_deg[i] = 0;
}

__global__ void k_build_edges(const int* __restrict__ members,
                              const int* __restrict__ centers,
                              const int* __restrict__ offsets) {
    int e = blockIdx.x * blockDim.x + threadIdx.x;
    if (e >= Ec) return;
    int s = offsets[e], t = offsets[e + 1];
    int list[ESTRIDE];
    int cnt = 0;
    for (int m = s; m < t && cnt < ESTRIDE; m++) {
        int n = members[m];
        bool dup = false;
        for (int k = 0; k < cnt; k++) if (list[k] == n) { dup = true; break; }
        if (!dup) list[cnt++] = n;
    }
    {
        int c = centers[e];
        bool dup = false;
        for (int k = 0; k < cnt; k++) if (list[k] == c) { dup = true; break; }
        if (!dup && cnt < ESTRIDE) list[cnt++] = c;
    }
    g_edge_cnt[e] = cnt;
    for (int k = 0; k < cnt; k++) {
        int n = list[k];
        g_edge_nodes[e * ESTRIDE + k] = n;
        int pos = atomicAdd(&g_node_deg[n], 1);
        if (pos < MAXD) g_node_edges[n * MAXD + pos] = e;
    }
    for (int k = cnt; k < ESTRIDE; k++) g_edge_nodes[e * ESTRIDE + k] = Nc;  // dummy zero row in xs
}

__global__ void k_sort_nodes() {
    int n = blockIdx.x * blockDim.x + threadIdx.x;
    if (n >= Nc) return;
    int d = g_node_deg[n];
    if (d > MAXD) d = MAXD;
    g_node_deg[n] = d;
    int* L = g_node_edges + n * MAXD;
    for (int i = 1; i < d; i++) {
        int key = L[i];
        int j = i - 1;
        while (j >= 0 && L[j] > key) { L[j + 1] = L[j]; j--; }
        L[j + 1] = key;
    }
    int d8 = (d + 7) & ~7;
    if (d8 > MAXD) d8 = MAXD;
    for (int i = d; i < d8; i++) L[i] = Ec;  // dummy: g_u row 1000 is zeroed
}

// ---------------- dynamic features: mean/std over T ----------------
__global__ void k_feat(const float* __restrict__ xraw) {
    int idx = blockIdx.x * blockDim.x + threadIdx.x;
    if (idx >= Bc * Nc * C_RAWc) return;
    int c = idx % C_RAWc;
    int n = (idx / C_RAWc) % Nc;
    int b = idx / (C_RAWc * Nc);
    float s1 = 0.f, s2 = 0.f;
    #pragma unroll
    for (int t = 0; t < Tc; t++) {
        float v = xraw[((b * Tc + t) * Nc + n) * C_RAWc + c];
        s1 += v; s2 += v * v;
    }
    float mean = s1 * (1.f / Tc);
    float var = s2 * (1.f / Tc) - mean * mean;
    if (var < 0.f) var = 0.f;
    g_feat[(b * Nc + n) * 16 + c] = mean;
    g_feat[(b * Nc + n) * 16 + C_RAWc + c] = sqrtf(var);
}

// ---------------- per-edge mean similarity (warp per (b,e)) ----------------
__global__ void k_sim(const int* __restrict__ members,
                      const int* __restrict__ centers,
                      const int* __restrict__ offsets) {
    int gid = blockIdx.x * (blockDim.x >> 5) + (threadIdx.x >> 5);
    if (gid >= Bc * Ec) return;
    int e = gid % Ec;
    int b = gid / Ec;
    int lane = threadIdx.x & 31;
    int s = offsets[e];
    int cntm = offsets[e + 1] - s;
    int cn = centers[e];
    const float4* cf4 = (const float4*)(g_feat + (b * Nc + cn) * 16);
    float4 c0 = cf4[0], c1 = cf4[1], c2 = cf4[2], c3 = cf4[3];
    float cn2 = c0.x*c0.x + c0.y*c0.y + c0.z*c0.z + c0.w*c0.w
              + c1.x*c1.x + c1.y*c1.y + c1.z*c1.z + c1.w*c1.w
              + c2.x*c2.x + c2.y*c2.y + c2.z*c2.z + c2.w*c2.w
              + c3.x*c3.x + c3.y*c3.y + c3.z*c3.z + c3.w*c3.w;
    float cnorm = sqrtf(cn2);
    float acc = 0.f;
    for (int m = lane; m < cntm; m += 32) {
        int n = members[s + m];
        const float4* mf4 = (const float4*)(g_feat + (b * Nc + n) * 16);
        float4 m0 = mf4[0], m1 = mf4[1], m2 = mf4[2], m3 = mf4[3];
        float dot = m0.x*c0.x + m0.y*c0.y + m0.z*c0.z + m0.w*c0.w
                  + m1.x*c1.x + m1.y*c1.y + m1.z*c1.z + m1.w*c1.w
                  + m2.x*c2.x + m2.y*c2.y + m2.z*c2.z + m2.w*c2.w
                  + m3.x*c3.x + m3.y*c3.y + m3.z*c3.z + m3.w*c3.w;
        float mn2 = m0.x*m0.x + m0.y*m0.y + m0.z*m0.z + m0.w*m0.w
                  + m1.x*m1.x + m1.y*m1.y + m1.z*m1.z + m1.w*m1.w
                  + m2.x*m2.x + m2.y*m2.y + m2.z*m2.z + m2.w*m2.w
                  + m3.x*m3.x + m3.y*m3.y + m3.z*m3.z + m3.w*m3.w;
        float sim = dot / (sqrtf(mn2) * cnorm + EPSc);
        acc += fminf(fmaxf(sim, 0.f), 1.f);
    }
    #pragma unroll
    for (int o = 16; o > 0; o >>= 1) acc += __shfl_xor_sync(FULLMASK, acc, o);
    if (lane == 0) {
        float count = (float)cntm;
        if (count < 1.f) count = 1.f;
        g_msum[b * Ec + e] = acc / count;
    }
}

// ---------------- per-batch min-max normalize -> Wd ----------------
__global__ void k_wd(const float* __restrict__ W) {
    int b = blockIdx.x;
    int tid = threadIdx.x;
    __shared__ float rmn[256], rmx[256];
    float mn = 1e30f, mx = -1e30f;
    for (int e = tid; e < Ec; e += 256) {
        float v = g_msum[b * Ec + e];
        mn = fminf(mn, v); mx = fmaxf(mx, v);
    }
    rmn[tid] = mn; rmx[tid] = mx;
    __syncthreads();
    for (int s = 128; s > 0; s >>= 1) {
        if (tid < s) {
            rmn[tid] = fminf(rmn[tid], rmn[tid + s]);
            rmx[tid] = fmaxf(rmx[tid], rmx[tid + s]);
        }
        __syncthreads();
    }
    mn = rmn[0]; mx = rmx[0];
    float inv = __fdividef(1.f, mx - mn + EPSc);
    for (int e = tid; e < Ec; e += 256) {
        float v = (g_msum[b * Ec + e] - mn) * inv;
        g_Wd[b * Ec + e] = W[e] * (1.f + LAMc * v);
    }
}

// ---------------- node degree weights -> dvi (warp per (b,n)) ----------------
__global__ void k_dvi() {
    int gid = blockIdx.x * (blockDim.x >> 5) + (threadIdx.x >> 5);
    if (gid >= Bc * Nc) return;
    int n = gid % Nc;
    int b = gid / Nc;
    int lane = threadIdx.x & 31;
    int d = g_node_deg[n];
    float s = 0.f;
    for (int i = lane; i < d; i += 32)
        s += g_Wd[b * Ec + g_node_edges[n * MAXD + i]];
    #pragma unroll
    for (int o = 16; o > 0; o >>= 1) s += __shfl_xor_sync(FULLMASK, s, o);
    if (lane == 0) g_dvi[gid] = rsqrtf(fmaxf(s, EPSc));
}

// ---------------- edge gather (+ fused input projection) ----------------
__global__ __launch_bounds__(512) void k_edge_gather(const float* __restrict__ x,
                                                     const float* __restrict__ ipw,
                                                     const float* __restrict__ ipb) {
    extern __shared__ float xs[];            // (Nc+1)*32
    float* sipw = xs + (Nc + 1) * 32;        // 512
    float* sipb = sipw + 512;                // 32
    int bt = blockIdx.x >> 1;
    int part = blockIdx.x & 1;
    int b = bt / Tc;

    if (threadIdx.x < 512) sipw[threadIdx.x] = ipw[threadIdx.x];
    if (threadIdx.x < 32) sipb[threadIdx.x] = ipb[threadIdx.x];
    __syncthreads();

    const float* xb = x + (size_t)bt * Nc * F_INc;
    float4* xs4 = (float4*)xs;
    for (int i = threadIdx.x; i < (Nc + 1) * 8; i += 512) {
        int n = i >> 3, q = (i & 7) * 4;
        float4 v = make_float4(0.f, 0.f, 0.f, 0.f);
        if (n < Nc) {
            const float* xr = xb + n * F_INc;
            float a0 = sipb[q], a1 = sipb[q + 1], a2 = sipb[q + 2], a3 = sipb[q + 3];
            #pragma unroll
            for (int k = 0; k < F_INc; k++) {
                float xv = xr[k];
                a0 += xv * sipw[k * 32 + q];
                a1 += xv * sipw[k * 32 + q + 1];
                a2 += xv * sipw[k * 32 + q + 2];
                a3 += xv * sipw[k * 32 + q + 3];
            }
            float d = g_dvi[b * Nc + n];
            v = make_float4(a0 * d, a1 * d, a2 * d, a3 * d);
        }
        xs4[i] = v;
    }
    __syncthreads();

    int lane = threadIdx.x & 31;
    int w = threadIdx.x >> 5;
    float* ub = g_u + ((size_t)bt << USH);
    int e0 = part * (Ec / 2);
    for (int e = e0 + w; e < e0 + Ec / 2; e += 16) {
        int cnt = g_edge_cnt[e];
        const int4* ip = (const int4*)(g_edge_nodes + e * ESTRIDE);
        int4 v0 = ip[0], v1 = ip[1], v2 = ip[2], v3 = ip[3], v4 = ip[4], v5 = ip[5];
        int idx[ESTRIDE] = {v0.x, v0.y, v0.z, v0.w, v1.x, v1.y, v1.z, v1.w,
                            v2.x, v2.y, v2.z, v2.w, v3.x, v3.y, v3.z, v3.w,
                            v4.x, v4.y, v4.z, v4.w, v5.x, v5.y, v5.z, v5.w};
        // 4 independent partial chains (depth 6) instead of one depth-24 chain
        float p0 = 0.f, p1 = 0.f, p2 = 0.f, p3 = 0.f;
        #pragma unroll
        for (int k = 0; k < ESTRIDE; k += 4) {
            p0 += xs[idx[k] * DMc + lane];
            p1 += xs[idx[k + 1] * DMc + lane];
            p2 += xs[idx[k + 2] * DMc + lane];
            p3 += xs[idx[k + 3] * DMc + lane];
        }
        float acc = (p0 + p1) + (p2 + p3);
        float sc = __fdividef(g_Wd[b * Ec + e], (float)cnt);
        ub[(e << 5) + lane] = acc * sc;
    }
    if (part) {  // zero pad rows 1000..1023 (dummy gather target)
        for (int e = Ec + w; e < 1024; e += 16) ub[(e << 5) + lane] = 0.f;
    }
}

// ---------------- fully fused: node gather + conv + [hc;h]@[wx;wh] + LSTM + head ----------------
// block = 4 warps x 4 rows = 16 rows; 500 blocks -> ~3.4 blocks/SM resident.
__global__ __launch_bounds__(128) void k_fused(
    const float* __restrict__ wx, const float* __restrict__ wh,
    const float* __restrict__ lb,
    const float* __restrict__ cwg, const float* __restrict__ cbg,
    const float* __restrict__ hw1, const float* __restrict__ hb1,
    const float* __restrict__ hw2, const float* __restrict__ hb2,
    float* __restrict__ out, int Pout) {
    extern __shared__ __align__(16) char smr[];
    u64*   sw01 = (u64*)smr;            // 2048: combined [wx;wh] gate pair (0,1)
    u64*   sw23 = sw01 + 2048;          // 2048: gate pair (2,3)
    u64*   sb01 = sw23 + 2048;          // 32
    u64*   sb23 = sb01 + 32;            // 32
    u64*   hb   = sb23 + 32;            // 4 warps * 4 rows * 64 slots = 1024
    float* cwS  = (float*)(hb + 1024);  // 1024
    float* cbS  = cwS + 1024;           // 32
    float* hw1S = cbS + 32;             // 1024
    float* hb1S = hw1S + 1024;          // 32
    float* hw2S = hb1S + 32;            // 384
    float* hb2S = hw2S + 384;           // 16
    float* sdvi = hb2S + 16;            // 16
    int*   sidx = (int*)(sdvi + 16);    // 16*64
    int*   sdeg = sidx + 1024;          // 16

    int tid = threadIdx.x;
    int rb = blockIdx.x * RPB;

    for (int idx = tid; idx < 2048; idx += 128) {
        int i = idx >> 5, l = idx & 31;
        const float* src = (i < 32) ? (wx + i * 128) : (wh + (i - 32) * 128);
        sw01[idx] = packab(src[l], src[32 + l]);
        sw23[idx] = packab(src[64 + l], src[96 + l]);
    }
    for (int idx = tid; idx < 1024; idx += 128) {
        cwS[idx] = cwg[idx];
        hw1S[idx] = hw1[idx];
        int row = rb + (idx >> 6);
        sidx[idx] = g_node_edges[(row % Nc) * MAXD + (idx & 63)];
    }
    for (int idx = tid; idx < 384; idx += 128) hw2S[idx] = hw2[idx];
    if (tid < 32) {
        sb01[tid] = packab(lb[tid], lb[32 + tid]);
        sb23[tid] = packab(lb[64 + tid], lb[96 + tid]);
        cbS[tid] = cbg[tid];
        hb1S[tid] = hb1[tid];
        if (tid < PREDc) hb2S[tid] = hb2[tid];
        if (tid < RPB) {
            int row = rb + tid;
            int b = row / Nc, n = row % Nc;
            sdvi[tid] = g_dvi[b * Nc + n];
            int d = g_node_deg[n];
            sdeg[tid] = (d + 7) & ~7;
        }
    }
    __syncthreads();

    int lane = tid & 31;
    int w = tid >> 5;
    u64* hbw = hb + w * (RPW * 64);

    int d8r[RPW], bTr[RPW];
    #pragma unroll
    for (int r = 0; r < RPW; r++) {
        int local = w * RPW + r;
        d8r[r] = sdeg[local];
        bTr[r] = ((rb + local) / Nc) * Tc;
    }

    float h[RPW], c[RPW];
    #pragma unroll
    for (int r = 0; r < RPW; r++) { h[r] = 0.f; c[r] = 0.f; }

    for (int t = 0; t < Tc; t++) {
        float hc[RPW];
        #pragma unroll
        for (int r = 0; r < RPW; r++) {
            const float* up = g_u + ((size_t)(bTr[r] + t) << USH);
            const int* L = sidx + (w * RPW + r) * 64;
            float p0 = 0.f, p1 = 0.f;
            for (int k0 = 0; k0 < d8r[r]; k0 += 8) {
                int4 a = *(const int4*)(L + k0);
                int4 b2 = *(const int4*)(L + k0 + 4);
                p0 += up[(a.x << 5) + lane] + up[(a.z << 5) + lane]
                    + up[(b2.x << 5) + lane] + up[(b2.z << 5) + lane];
                p1 += up[(a.y << 5) + lane] + up[(a.w << 5) + lane]
                    + up[(b2.y << 5) + lane] + up[(b2.w << 5) + lane];
            }
            float acc = (p0 + p1) * sdvi[w * RPW + r];
            float z = cbS[lane];
            #pragma unroll 8
            for (int f = 0; f < DMc; f++)
                z += __shfl_sync(FULLMASK, acc, f) * cwS[f * 32 + lane];
            hc[r] = siluf(z);
        }
        __syncwarp();
        #pragma unroll
        for (int r = 0; r < RPW; r++) {
            hbw[r * 64 + lane] = pack11(hc[r]);
            hbw[r * 64 + 32 + lane] = pack11(h[r]);
        }
        __syncwarp();
        u64 z01[RPW], z23[RPW];
        #pragma unroll
        for (int r = 0; r < RPW; r++) { z01[r] = sb01[lane]; z23[r] = sb23[lane]; }
        #pragma unroll 8
        for (int i = 0; i < 64; i++) {
            u64 w01 = sw01[(i << 5) + lane];
            u64 w23 = sw23[(i << 5) + lane];
            #pragma unroll
            for (int r = 0; r < RPW; r++) {
                u64 hv = hbw[r * 64 + i];
                ffma2(z01[r], hv, w01);
                ffma2(z23[r], hv, w23);
            }
        }
        #pragma unroll
        for (int r = 0; r < RPW; r++) {
            float2 zif = unpk(z01[r]);
            float2 zgo = unpk(z23[r]);
            float ig = sigmf(zif.x);
            float fg = sigmf(zif.y);
            float gg = tanhf_(zgo.x);
            float og = sigmf(zgo.y);
            c[r] = fg * c[r] + ig * gg;
            h[r] = og * tanhf_(c[r]);
        }
    }

    // head: y = silu(h @ hw1 + hb1) @ hw2 + hb2
    #pragma unroll
    for (int r = 0; r < RPW; r++) {
        int row = rb + w * RPW + r;
        int b = row / Nc;
        int n = row % Nc;
        float a = hb1S[lane];
        #pragma unroll 8
        for (int i = 0; i < 32; i++) {
            float hi = __shfl_sync(FULLMASK, h[r], i);
            a += hi * hw1S[i * 32 + lane];
        }
        float y1 = siluf(a);
        float o = (lane < PREDc) ? hb2S[lane] : 0.f;
        #pragma unroll 8
        for (int j = 0; j < 32; j++) {
            float yj = __shfl_sync(FULLMASK, y1, j);
            if (lane < PREDc) o += yj * hw2S[j * PREDc + lane];
        }
        if (lane < Pout) out[((size_t)b * Pout + lane) * Nc + n] = o;
    }
}

// ---------------- launch ----------------
extern "C" void kernel_launch(void* const* d_in, const int* in_sizes, int n_in,
                              void* d_out, int out_size) {
    const float* x       = (const float*)d_in[0];
    const float* xraw    = (const float*)d_in[1];
    const float* W       = (const float*)d_in[3];
    const int*   members = (const int*)d_in[4];
    const int*   centers = (const int*)d_in[5];
    const int*   offsets = (const int*)d_in[6];
    const float* ipw     = (const float*)d_in[7];
    const float* ipb     = (const float*)d_in[8];
    const float* cw      = (const float*)d_in[9];
    const float* cb      = (const float*)d_in[10];
    const float* wx      = (const float*)d_in[11];
    const float* wh      = (const float*)d_in[12];
    const float* lb      = (const float*)d_in[13];
    const float* hw1     = (const float*)d_in[14];
    const float* hb1     = (const float*)d_in[15];
    const float* hw2     = (const float*)d_in[16];
    const float* hb2     = (const float*)d_in[17];
    float* out = (float*)d_out;
    int Pout = out_size / (Bc * Nc);

    int smem_edge = ((Nc + 1) * 32 + 512 + 32) * sizeof(float);  // 130304
    int smem_fused = 5184 * sizeof(u64) + 2528 * sizeof(float) + 1040 * sizeof(int);  // 55744
    cudaFuncSetAttribute(k_edge_gather, cudaFuncAttributeMaxDynamicSharedMemorySize, smem_edge);
    cudaFuncSetAttribute(k_fused, cudaFuncAttributeMaxDynamicSharedMemorySize, smem_fused);

    k_zero_deg<<<4, 256>>>();
    k_build_edges<<<4, 256>>>(members, centers, offsets);
    k_sort_nodes<<<4, 256>>>();
    k_feat<<<(Bc * Nc * C_RAWc + 255) / 256, 256>>>(xraw);
    k_sim<<<(Bc * Ec + 7) / 8, 256>>>(members, centers, offsets);
    k_wd<<<Bc, 256>>>(W);
    k_dvi<<<(Bc * Nc + 7) / 8, 256>>>();
    k_edge_gather<<<Bc * Tc * 2, 512, smem_edge>>>(x, ipw, ipb);
    k_fused<<<Bc * Nc / RPB, 128, smem_fused>>>(wx, wh, lb, cw, cb,
                                                hw1, hb1, hw2, hb2, out, Pout);
}